// round 12
// baseline (speedup 1.0000x reference)
#include <cuda_runtime.h>
#include <cuda.h>

#define N_BINS 10
#define TILE_ROWS 192
#define TILE_BYTES (TILE_ROWS * 512)
#define TMA_GRID 148
#define TMA_THREADS 192
#define DSM_BYTES (2 * TILE_BYTES + 1024)

// Fallback (warp-per-pair) config
#define FB_GRID 1184
#define FB_THREADS 256
#define FB_WARPS (FB_GRID * (FB_THREADS / 32))

// Global scratch (no allocations allowed). Zero-initialized at module load;
// the last finishing block resets them each launch.
__device__ double g_cnt[N_BINS];
__device__ double g_conf[N_BINS];
__device__ double g_acc[N_BINS];
__device__ unsigned g_done;

__device__ __forceinline__ float expf_raw(float x) {
    float t = __fmul_rn(x, 1.4426950408889634f);
    float r;
    asm("ex2.approx.f32 %0, %1;" : "=f"(r) : "f"(t));
    return r;
}

__device__ __forceinline__ unsigned smem_u32(const void* p) {
    return (unsigned)__cvta_generic_to_shared(p);
}

__device__ __forceinline__ void mbar_init(unsigned mbar, unsigned cnt) {
    asm volatile("mbarrier.init.shared.b64 [%0], %1;" :: "r"(mbar), "r"(cnt) : "memory");
}
__device__ __forceinline__ void mbar_expect_tx(unsigned mbar, unsigned tx) {
    asm volatile("mbarrier.arrive.expect_tx.shared.b64 _, [%0], %1;"
                 :: "r"(mbar), "r"(tx) : "memory");
}
__device__ __forceinline__ void mbar_wait_parity(unsigned mbar, unsigned ph) {
    asm volatile(
        "{\n\t.reg .pred P1;\n\t"
        "WAIT_%=:\n\t"
        "mbarrier.try_wait.parity.acquire.cta.shared::cta.b64 P1, [%0], %1, 0x989680;\n\t"
        "@P1 bra DONE_%=;\n\t"
        "bra WAIT_%=;\n\t"
        "DONE_%=:\n\t}"
        :: "r"(mbar), "r"(ph) : "memory");
}
__device__ __forceinline__ void tma_load_tile(unsigned dst, const CUtensorMap* tm,
                                              int z, unsigned mbar) {
    asm volatile(
        "cp.async.bulk.tensor.3d.shared::cta.global.tile.mbarrier::complete_tx::bytes "
        "[%0], [%1, {%2, %3, %4}], [%5];"
        :: "r"(dst), "l"(tm), "r"(0), "r"(0), "r"(z), "r"(mbar) : "memory");
}

// Shared finalize: last block of n_blocks computes outputs and resets scratch.
__device__ __forceinline__ void finalize_maybe(float* out, int n_rows, int n_blocks) {
    unsigned ticket = atomicAdd(&g_done, 1u);
    if (ticket == (unsigned)(n_blocks - 1)) {
        double ece = 0.0, oe = 0.0;
        #pragma unroll
        for (int i = 0; i < N_BINS; i++) {
            double cnt = atomicAdd(&g_cnt[i],  0.0);
            double cf  = atomicAdd(&g_conf[i], 0.0);
            double ac  = atomicAdd(&g_acc[i],  0.0);
            bool nonempty = cnt > 0.0;
            double prop  = cnt / (double)n_rows;
            double denom = nonempty ? cnt : 1.0;
            double accb  = nonempty ? ac / denom : 0.0;
            double cfb   = nonempty ? cf / denom : 0.0;
            double CE    = cfb - accb;
            double absCE = nonempty ? fabs(CE) : 0.0;
            ece += absCE * prop;
            oe  += (nonempty ? cfb * fmax(CE, 0.0) : 0.0) * prop;
            out[1 + i]  = (float)accb;
            out[12 + i] = (float)prop;
            out[22 + i] = (float)absCE;
            g_cnt[i] = 0.0; g_conf[i] = 0.0; g_acc[i] = 0.0;
        }
        out[0]  = (float)ece;
        out[11] = (float)oe;
        g_done = 0u;
        __threadfence();
    }
}

// ===================== TMA path: thread-per-row =====================
__global__ void __launch_bounds__(TMA_THREADS) ece_tma(
    const __grid_constant__ CUtensorMap tmap,
    const int* __restrict__ labels,
    int n_rows,
    float* __restrict__ out)
{
    extern __shared__ char dsm_raw[];
    char* dsm = (char*)(((uintptr_t)dsm_raw + 1023) & ~(uintptr_t)1023);

    __shared__ unsigned long long mbar[2];
    __shared__ float s_c[N_BINS], s_f[N_BINS], s_a[N_BINS];

    const int tid = threadIdx.x;
    const int r   = tid;               // my row within the tile
    if (tid < N_BINS) { s_c[tid] = 0.0f; s_f[tid] = 0.0f; s_a[tid] = 0.0f; }

    const unsigned mb0 = smem_u32(&mbar[0]);
    const unsigned mb1 = smem_u32(&mbar[1]);
    const unsigned sbuf0 = smem_u32(dsm);
    const unsigned sbuf1 = smem_u32(dsm + TILE_BYTES);

    if (tid == 0) { mbar_init(mb0, 1); mbar_init(mb1, 1); }
    __syncthreads();

    const int n_tiles = (n_rows + TILE_ROWS - 1) / TILE_ROWS;

    // Prologue: this block's first two tiles.
    if (tid == 0) {
        if (blockIdx.x < n_tiles) {
            mbar_expect_tx(mb0, TILE_BYTES);
            tma_load_tile(sbuf0, &tmap, blockIdx.x * TILE_ROWS, mb0);
        }
        int t1 = blockIdx.x + TMA_GRID;
        if (t1 < n_tiles) {
            mbar_expect_tx(mb1, TILE_BYTES);
            tma_load_tile(sbuf1, &tmap, t1 * TILE_ROWS, mb1);
        }
    }

    const int rx = r & 7;
    int i = 0;
    for (int t = blockIdx.x; t < n_tiles; t += TMA_GRID, i++) {
        const int st = i & 1;
        const unsigned mb = st ? mb1 : mb0;
        const char* buf = dsm + st * TILE_BYTES;

        mbar_wait_parity(mb, (i >> 1) & 1);

        // ---- scalar scan of my row (conflict-free swizzled order) ----
        const char* rb = buf + r * 512;
        float s0 = 0.f, s1 = 0.f, s2 = 0.f, s3 = 0.f;
        float mA = -1e30f, mB = -1e30f;
        #pragma unroll
        for (int k = 0; k < 32; k++) {
            int off = ((k & 24) | ((k ^ rx) & 7)) << 4;
            float4 v = *(const float4*)(rb + off);
            mA = fmaxf(mA, fmaxf(v.x, v.y));
            mB = fmaxf(mB, fmaxf(v.z, v.w));
            s0 += expf_raw(v.x);
            s1 += expf_raw(v.y);
            s2 += expf_raw(v.z);
            s3 += expf_raw(v.w);
        }
        const int gr = t * TILE_ROWS + r;
        if (gr < n_rows) {
            float mx = fmaxf(mA, mB);
            float s  = (s0 + s1) + (s2 + s3);
            float conf = __fdividef(expf_raw(mx), s);   // bit-exact numerator

            int lab = labels[gr];
            int a  = r * 512 + lab * 4;
            int sw = a ^ ((a >> 3) & 0x70);             // SW128
            float lv = *(const float*)(buf + sw);

            int b = min((int)ceilf(conf * 10.0f), N_BINS) - 1;
            b = max(b, 0);
            atomicAdd(&s_c[b], 1.0f);
            atomicAdd(&s_f[b], conf);
            atomicAdd(&s_a[b], (lv == mx) ? 1.0f : 0.0f);
        }
        __syncthreads();   // all reads of buf done before refilling it

        if (tid == 0) {
            int t2 = t + 2 * TMA_GRID;
            if (t2 < n_tiles) {
                mbar_expect_tx(mb, TILE_BYTES);
                tma_load_tile(st ? sbuf1 : sbuf0, &tmap, t2 * TILE_ROWS, mb);
            }
        }
    }

    __syncthreads();
    if (tid < N_BINS) {
        atomicAdd(&g_cnt[tid],  (double)s_c[tid]);
        atomicAdd(&g_conf[tid], (double)s_f[tid]);
        atomicAdd(&g_acc[tid],  (double)s_a[tid]);
        __threadfence();
    }
    __syncthreads();
    if (tid == 0) finalize_maybe(out, n_rows, TMA_GRID);
}

// ===================== Fallback: proven warp-per-pair (R9) =====================
__device__ __forceinline__ void fb_pair(
    float4 A, float4 B, int lab, unsigned mask, int hl,
    bool acc_en, float& r_cnt, float& r_conf, float& r_acc)
{
    const float L2E = 1.4426950408889634f;
    float e0 = expf_raw(0.f), dummy = e0; (void)dummy;
    float x0, x1, x2, x3, x4, x5, x6, x7;
    {
        float t;
        asm("ex2.approx.f32 %0, %1;" : "=f"(x0) : "f"(fmaf(A.x, L2E, 16.0f)));
        asm("ex2.approx.f32 %0, %1;" : "=f"(x1) : "f"(fmaf(A.y, L2E, 16.0f)));
        asm("ex2.approx.f32 %0, %1;" : "=f"(x2) : "f"(fmaf(A.z, L2E, 16.0f)));
        asm("ex2.approx.f32 %0, %1;" : "=f"(x3) : "f"(fmaf(A.w, L2E, 16.0f)));
        asm("ex2.approx.f32 %0, %1;" : "=f"(x4) : "f"(fmaf(B.x, L2E, 16.0f)));
        asm("ex2.approx.f32 %0, %1;" : "=f"(x5) : "f"(fmaf(B.y, L2E, 16.0f)));
        asm("ex2.approx.f32 %0, %1;" : "=f"(x6) : "f"(fmaf(B.z, L2E, 16.0f)));
        asm("ex2.approx.f32 %0, %1;" : "=f"(x7) : "f"(fmaf(B.w, L2E, 16.0f)));
        (void)t;
    }
    float s = ((x0 + x1) + (x2 + x3)) + ((x4 + x5) + (x6 + x7));
    unsigned usum = __reduce_add_sync(mask, __float2uint_rn(s));
    float m = fmaxf(fmaxf(fmaxf(x0, x1), fmaxf(x2, x3)),
                    fmaxf(fmaxf(x4, x5), fmaxf(x6, x7)));
    int sub = lab & 3;
    float elo = (sub & 2) ? ((sub & 1) ? x3 : x2) : ((sub & 1) ? x1 : x0);
    float ehi = (sub & 2) ? ((sub & 1) ? x7 : x6) : ((sub & 1) ? x5 : x4);
    float vl  = (lab & 64) ? ehi : elo;
    unsigned bit = (((lab >> 2) & 15) == hl) && (vl == m);
    unsigned wk = __reduce_max_sync(mask, (__float_as_uint(m) << 1) | bit);
    float wm = __uint_as_float(wk >> 1);
    float conf = __fdividef(wm, __uint2float_rn(usum));
    int b1 = min((int)ceilf(conf * 10.0f), N_BINS);
    if (acc_en && b1 == hl + 1) {
        r_cnt += 1.0f; r_conf += conf; r_acc += (float)(wk & 1u);
    }
}

__global__ void __launch_bounds__(FB_THREADS, 8) ece_fallback(
    const float* __restrict__ logits,
    const int* __restrict__ labels,
    int n_rows,
    float* __restrict__ out)
{
    __shared__ float s_c[N_BINS], s_f[N_BINS], s_a[N_BINS];
    int tid = threadIdx.x;
    if (tid < N_BINS) { s_c[tid] = 0.0f; s_f[tid] = 0.0f; s_a[tid] = 0.0f; }

    const int lane = tid & 31;
    const int half = lane >> 4;
    const int hl   = lane & 15;
    const unsigned mask = 0xFFFFu << (half << 4);
    const int gwarp = blockIdx.x * (FB_THREADS / 32) + (tid >> 5);
    const float4* __restrict__ lrows = (const float4*)logits;

    float r_cnt = 0.f, r_conf = 0.f, r_acc = 0.f;
    const int n_pairs = n_rows >> 1;
    const float4* p = lrows + (size_t)gwarp * 64 + (half << 5) + hl;
    const int2* lp = (const int2*)labels + gwarp;

    #pragma unroll 1
    for (int pr = gwarp; pr < n_pairs; pr += FB_WARPS) {
        float4 A = p[0];
        float4 B = p[16];
        int2 L = *lp;
        fb_pair(A, B, half ? L.y : L.x, mask, hl, true, r_cnt, r_conf, r_acc);
        p += (size_t)FB_WARPS * 64;
        lp += FB_WARPS;
    }
    if (gwarp == 0) {
        for (int r2 = n_pairs * 2; r2 < n_rows; r2++) {
            const float4* q = lrows + (size_t)r2 * 32 + hl;
            float4 A = q[0], B = q[16];
            fb_pair(A, B, labels[r2], mask, hl, half == 0, r_cnt, r_conf, r_acc);
        }
    }

    __syncthreads();
    if (hl < N_BINS) {
        atomicAdd(&s_c[hl], r_cnt);
        atomicAdd(&s_f[hl], r_conf);
        atomicAdd(&s_a[hl], r_acc);
    }
    __syncthreads();
    if (tid < N_BINS) {
        atomicAdd(&g_cnt[tid],  (double)s_c[tid]);
        atomicAdd(&g_conf[tid], (double)s_f[tid]);
        atomicAdd(&g_acc[tid],  (double)s_a[tid]);
        __threadfence();
    }
    __syncthreads();
    if (tid == 0) finalize_maybe(out, n_rows, FB_GRID);
}

// ===================== host =====================
typedef CUresult (*EncodeTiledFn)(
    CUtensorMap*, CUtensorMapDataType, cuuint32_t, void*,
    const cuuint64_t*, const cuuint64_t*, const cuuint32_t*, const cuuint32_t*,
    CUtensorMapInterleave, CUtensorMapSwizzle, CUtensorMapL2promotion,
    CUtensorMapFloatOOBfill);

extern "C" void kernel_launch(void* const* d_in, const int* in_sizes, int n_in,
                              void* d_out, int out_size) {
    const float* logits = (const float*)d_in[0];
    const int*   labels = (const int*)d_in[1];
    float*       out    = (float*)d_out;
    int n_rows = in_sizes[0] / 128;   // C = 128

    // Try the TMA path: build a tensor map via the runtime's driver entry point.
    bool tma_ok = false;
    alignas(64) CUtensorMap tmap;
    void* fp = nullptr;
    cudaDriverEntryPointQueryResult qr = cudaDriverEntryPointSymbolNotFound;
    if (cudaGetDriverEntryPoint("cuTensorMapEncodeTiled", &fp,
                                cudaEnableDefault, &qr) == cudaSuccess &&
        qr == cudaDriverEntryPointSuccess && fp) {
        cuuint64_t dims[3]    = {32, 4, (cuuint64_t)n_rows};
        cuuint64_t strides[2] = {128, 512};
        cuuint32_t box[3]     = {32, 4, TILE_ROWS};
        cuuint32_t estr[3]    = {1, 1, 1};
        CUresult r = ((EncodeTiledFn)fp)(
            &tmap, CU_TENSOR_MAP_DATA_TYPE_FLOAT32, 3, (void*)logits,
            dims, strides, box, estr,
            CU_TENSOR_MAP_INTERLEAVE_NONE, CU_TENSOR_MAP_SWIZZLE_128B,
            CU_TENSOR_MAP_L2_PROMOTION_L2_128B,
            CU_TENSOR_MAP_FLOAT_OOB_FILL_NONE);
        if (r == CUDA_SUCCESS) {
            if (cudaFuncSetAttribute(ece_tma,
                    cudaFuncAttributeMaxDynamicSharedMemorySize,
                    DSM_BYTES) == cudaSuccess)
                tma_ok = true;
        }
    }

    if (tma_ok) {
        ece_tma<<<TMA_GRID, TMA_THREADS, DSM_BYTES>>>(tmap, labels, n_rows, out);
    } else {
        ece_fallback<<<FB_GRID, FB_THREADS>>>(logits, labels, n_rows, out);
    }
}

// round 13
// speedup vs baseline: 4.6394x; 4.6394x over previous
#include <cuda_runtime.h>

#define N_BINS 10
#define GRID_BLOCKS 1184    // 148 SMs * 8 blocks -> one wave at full occupancy
#define BLOCK_THREADS 256
#define TOTAL_WARPS (GRID_BLOCKS * (BLOCK_THREADS / 32))

// Global scratch (no allocations allowed). Zero-initialized at module load;
// the last finishing block resets them, so "zeroed at entry" holds across
// graph replays.
__device__ double g_cnt[N_BINS];
__device__ double g_conf[N_BINS];
__device__ double g_acc[N_BINS];
__device__ unsigned g_done;

__device__ __forceinline__ float ex2(float x) {
    float r;
    asm("ex2.approx.f32 %0, %1;" : "=f"(r) : "f"(x));
    return r;
}

// Two rows per warp: lanes 0-15 handle one row, lanes 16-31 the next.
// All cross-lane reduction uses full-constant-mask shfl_xor with offsets
// 8,4,2,1 -- these never cross the 16-lane boundary, so each half reduces
// independently while every SHFL is a single hardware instruction.
// Each lane holds 8 columns of its row: cols 4*hl..4*hl+3 (A) and
// 64+4*hl..64+4*hl+3 (B). lab = label of THIS lane's row.
// Lane hl of each half accumulates bin hl.
__device__ __forceinline__ void ece_pair(
    float4 A, float4 B, int lab, int hl,
    bool acc_en,
    float& r_cnt, float& r_conf, float& r_acc)
{
    const float L2E = 1.4426950408889634f;
    float e0 = ex2(A.x * L2E);
    float e1 = ex2(A.y * L2E);
    float e2 = ex2(A.z * L2E);
    float e3 = ex2(A.w * L2E);
    float e4 = ex2(B.x * L2E);
    float e5 = ex2(B.y * L2E);
    float e6 = ex2(B.z * L2E);
    float e7 = ex2(B.w * L2E);

    // Local sum + local max of the 8 exps.
    float s = ((e0 + e1) + (e2 + e3)) + ((e4 + e5) + (e6 + e7));
    float m = fmaxf(fmaxf(fmaxf(e0, e1), fmaxf(e2, e3)),
                    fmaxf(fmaxf(e4, e5), fmaxf(e6, e7)));

    // Does MY lane own the label column, and does it attain my local max?
    int sub = lab & 3;
    float elo = (sub & 2) ? ((sub & 1) ? e3 : e2) : ((sub & 1) ? e1 : e0);
    float ehi = (sub & 2) ? ((sub & 1) ? e7 : e6) : ((sub & 1) ? e5 : e4);
    float vl  = (lab & 64) ? ehi : elo;
    unsigned bit = (((lab >> 2) & 15) == hl) && (vl == m);

    // Packed key: exps are positive (bits < 2^31), so (bits<<1)|correct is
    // order-preserving in m.
    unsigned k = (__float_as_uint(m) << 1) | bit;

    // Segmented butterfly reduction within each 16-lane half.
    #pragma unroll
    for (int o = 8; o; o >>= 1) {
        s += __shfl_xor_sync(0xffffffffu, s, o);
        unsigned ok = __shfl_xor_sync(0xffffffffu, k, o);
        k = max(k, ok);
    }
    float wm = __uint_as_float(k >> 1);

    float conf = __fdividef(wm, s);                       // max softmax prob
    int b1 = min((int)ceilf(conf * 10.0f), N_BINS);       // in [1,10]
    if (acc_en && b1 == hl + 1) {
        r_cnt  += 1.0f;
        r_conf += conf;
        r_acc  += (float)(k & 1u);
    }
}

__global__ void __launch_bounds__(BLOCK_THREADS, 8) ece_fused(
    const float* __restrict__ logits,
    const int* __restrict__ labels,
    int n_rows,
    float* __restrict__ out)
{
    __shared__ float s_c[N_BINS], s_f[N_BINS], s_a[N_BINS];

    int tid = threadIdx.x;
    if (tid < N_BINS) { s_c[tid] = 0.0f; s_f[tid] = 0.0f; s_a[tid] = 0.0f; }

    const int lane  = tid & 31;
    const int half  = lane >> 4;           // 0: even row of pair, 1: odd row
    const int hl    = lane & 15;
    const int warp  = tid >> 5;
    const int gwarp = blockIdx.x * (BLOCK_THREADS / 32) + warp;

    const float4* __restrict__ lrows = (const float4*)logits;

    float r_cnt = 0.0f, r_conf = 0.0f, r_acc = 0.0f;

    // One pair (2 rows = 1KB) per iteration; 64-warp TLP hides latency.
    const int n_pairs = n_rows >> 1;
    const float4* __restrict__ p = lrows + (size_t)gwarp * 64 + (half << 5) + hl;
    const int2*   __restrict__ lp = (const int2*)labels + gwarp;

    #pragma unroll 1
    for (int pr = gwarp; pr < n_pairs; pr += TOTAL_WARPS) {
        float4 A = p[0];
        float4 B = p[16];
        int2   L = *lp;
        ece_pair(A, B, half ? L.y : L.x, hl, true, r_cnt, r_conf, r_acc);
        p  += (size_t)TOTAL_WARPS * 64;
        lp += TOTAL_WARPS;
    }

    // Odd leftover row (n_rows odd): warp 0 handles it, halves mirror the row.
    if (gwarp == 0) {
        for (int r = n_pairs * 2; r < n_rows; r++) {
            const float4* q = lrows + (size_t)r * 32 + hl;
            float4 A = q[0], B = q[16];
            ece_pair(A, B, labels[r], hl, half == 0, r_cnt, r_conf, r_acc);
        }
    }

    // Block reduction: lane hl (<10) of each half holds bin hl partials.
    __syncthreads();                   // also covers the s_* zero-init
    if (hl < N_BINS) {
        atomicAdd(&s_c[hl], r_cnt);
        atomicAdd(&s_f[hl], r_conf);
        atomicAdd(&s_a[hl], r_acc);
    }
    __syncthreads();

    if (tid < N_BINS) {
        atomicAdd(&g_cnt[tid],  (double)s_c[tid]);
        atomicAdd(&g_conf[tid], (double)s_f[tid]);
        atomicAdd(&g_acc[tid],  (double)s_a[tid]);
        __threadfence();               // order bin atomics before done-ticket
    }
    __syncthreads();

    // Last block finalizes and resets scratch for the next graph replay.
    if (tid == 0) {
        unsigned ticket = atomicAdd(&g_done, 1u);
        if (ticket == GRID_BLOCKS - 1) {
            double ece = 0.0, oe = 0.0;
            #pragma unroll
            for (int i = 0; i < N_BINS; i++) {
                double cnt = atomicAdd(&g_cnt[i],  0.0);
                double cf  = atomicAdd(&g_conf[i], 0.0);
                double ac  = atomicAdd(&g_acc[i],  0.0);
                bool nonempty = cnt > 0.0;
                double prop  = cnt / (double)n_rows;
                double denom = nonempty ? cnt : 1.0;
                double accb  = nonempty ? ac / denom : 0.0;
                double cfb   = nonempty ? cf / denom : 0.0;
                double CE    = cfb - accb;
                double absCE = nonempty ? fabs(CE) : 0.0;
                ece += absCE * prop;
                oe  += (nonempty ? cfb * fmax(CE, 0.0) : 0.0) * prop;
                out[1 + i]  = (float)accb;
                out[12 + i] = (float)prop;
                out[22 + i] = (float)absCE;
                g_cnt[i] = 0.0; g_conf[i] = 0.0; g_acc[i] = 0.0;
            }
            out[0]  = (float)ece;
            out[11] = (float)oe;
            g_done = 0u;
            __threadfence();
        }
    }
}

extern "C" void kernel_launch(void* const* d_in, const int* in_sizes, int n_in,
                              void* d_out, int out_size) {
    const float* logits = (const float*)d_in[0];
    const int*   labels = (const int*)d_in[1];
    float*       out    = (float*)d_out;

    int n_rows = in_sizes[0] / 128;   // C = 128

    ece_fused<<<GRID_BLOCKS, BLOCK_THREADS>>>(logits, labels, n_rows, out);
}